// round 15
// baseline (speedup 1.0000x reference)
#include <cuda_runtime.h>

#define BMAX 32
#define H 512
#define W 512
#define HW (H*W)
#define NB 256
#define HIST_BLOCKS 32
#define NREP 8

#define TW 256     // blur output tile width
#define TH 32      // blur tile height
#define VC 66      // vtile float4 columns (64 main + 2 halo)

// Gaussian weights, constant-folded (fp32 immediates)
#define KE1 0.6065306597126334
#define KE2 0.1353352832366127
#define KE3 0.011108996538242306
#define KE4 0.00033546262790251185
#define KSUM (1.0 + 2.0 * (KE1 + KE2 + KE3 + KE4))
#define GW0 ((float)(KE4 / KSUM))
#define GW1 ((float)(KE3 / KSUM))
#define GW2 ((float)(KE2 / KSUM))
#define GW3 ((float)(KE1 / KSUM))
#define GW4 ((float)(1.0 / KSUM))

// Scratch (device globals — static init only; no runtime allocation)
__device__ float    g_blurred[BMAX * HW];        // 32 MiB
__device__ unsigned g_hist[BMAX * NB];           // zero-init
#define S8 0x7f7f7f7f,0x7f7f7f7f,0x7f7f7f7f,0x7f7f7f7f,0x7f7f7f7f,0x7f7f7f7f,0x7f7f7f7f,0x7f7f7f7f
__device__ int      g_min[BMAX] = {S8, S8, S8, S8};  // +big sentinel (first run)
__device__ int      g_max[BMAX];                     // zero-init (values >= 0)
__device__ unsigned g_done[BMAX];                    // zero-init
__device__ float    g_thresh[BMAX];

__device__ __forceinline__ float thermal(float v) {
    return __saturatef(__fmaf_rn(v, 0.5f, 0.5f));
}

// ---------------------------------------------------------------------------
// 1) thermal + separable Gaussian blur (edge-replicate) + per-image min/max.
//    Proven configuration (18.6us): TH=32, static smem, 8 rows/thread.
// ---------------------------------------------------------------------------
__global__ __launch_bounds__(VC * 4) void blur_kernel(const float* __restrict__ x) {
    __shared__ float4 vtile[TH][VC];   // 33,792 B

    const int b       = blockIdx.z;
    const int tile_x0 = blockIdx.x * TW;
    const int tile_y0 = blockIdx.y * TH;
    const int tx      = threadIdx.x;   // 0..65
    const int ty      = threadIdx.y;   // 0..3
    const float4* __restrict__ img4 =
        reinterpret_cast<const float4*>(x + (size_t)b * 4 * HW);   // channel 0

    const float k[9] = {GW0, GW1, GW2, GW3, GW4, GW3, GW2, GW1, GW0};

    const int  c4  = blockIdx.x * 64 + tx - 1;
    const int  c4c = min(max(c4, 0), 127);
    const int  y0  = tile_y0 + ty * 8;

    float4 ring[9];

    #define LOADROW(DST, Y) do {                                         \
        int yy = min(max((Y), 0), H - 1);                                \
        float4 v = img4[yy * 128 + c4c];                                 \
        v.x = thermal(v.x); v.y = thermal(v.y);                          \
        v.z = thermal(v.z); v.w = thermal(v.w);                          \
        (DST) = v;                                                       \
    } while (0)

    #pragma unroll
    for (int i = 0; i < 8; i++) LOADROW(ring[i], y0 - 4 + i);

    #pragma unroll
    for (int j = 0; j < 8; j++) {
        LOADROW(ring[(j + 8) % 9], y0 + 4 + j);
        float4 acc = make_float4(0.f, 0.f, 0.f, 0.f);
        #pragma unroll
        for (int d = 0; d < 9; d++) {
            float4 r = ring[(j + d) % 9];
            acc.x += k[d] * r.x;
            acc.y += k[d] * r.y;
            acc.z += k[d] * r.z;
            acc.w += k[d] * r.w;
        }
        vtile[ty * 8 + j][tx] = acc;
    }
    __syncthreads();

    const int tid = ty * VC + tx;
    if (tid < 256) {
        const int j4 = tid & 63;
        const int rg = tid >> 6;

        const bool lft = (tile_x0 == 0)      && (j4 == 0);
        const bool rgt = (tile_x0 == W - TW) && (j4 == 63);

        float lmin = 1e30f, lmax = -1e30f;
        float* __restrict__ dst = g_blurred + (size_t)b * HW;

        #pragma unroll
        for (int jr = 0; jr < 8; jr++) {
            const int r = rg * 8 + jr;
            float4 a  = vtile[r][j4];
            float4 bq = vtile[r][j4 + 1];
            float4 cq = vtile[r][j4 + 2];
            if (lft) { a.y = a.x;  a.z = a.x;  a.w = a.x;  }
            if (rgt) { cq.x = cq.w; cq.y = cq.w; cq.z = cq.w; }
            float w[12] = {a.x, a.y, a.z, a.w, bq.x, bq.y, bq.z, bq.w,
                           cq.x, cq.y, cq.z, cq.w};
            float4 o = make_float4(0.f, 0.f, 0.f, 0.f);
            #pragma unroll
            for (int d = 0; d < 9; d++) {
                o.x += k[d] * w[d];
                o.y += k[d] * w[d + 1];
                o.z += k[d] * w[d + 2];
                o.w += k[d] * w[d + 3];
            }
            reinterpret_cast<float4*>(dst + (size_t)(tile_y0 + r) * W)
                [tile_x0 / 4 + j4] = o;
            lmin = fminf(lmin, fminf(fminf(o.x, o.y), fminf(o.z, o.w)));
            lmax = fmaxf(lmax, fmaxf(fmaxf(o.x, o.y), fmaxf(o.z, o.w)));
        }

        #pragma unroll
        for (int off = 16; off > 0; off >>= 1) {
            lmin = fminf(lmin, __shfl_xor_sync(0xffffffffu, lmin, off));
            lmax = fmaxf(lmax, __shfl_xor_sync(0xffffffffu, lmax, off));
        }
        if ((tid & 31) == 0) {   // values >= 0 -> int compare == float compare
            atomicMin(&g_min[b], __float_as_int(lmin));
            atomicMax(&g_max[b], __float_as_int(lmax));
        }
    }
}

// ---------------------------------------------------------------------------
// 2) histogram + fused Otsu; PDL: smem init before the grid-dep sync.
// ---------------------------------------------------------------------------
__device__ __forceinline__ int binof(float v, float lo, float inv_wm) {
    return min(max(__float2int_rd((v - lo) * inv_wm), 0), 255);
}

__global__ void hist_otsu_kernel() {
    __shared__ unsigned h[NREP][NB];   // 8 KiB
    __shared__ bool s_last;
    const int b = blockIdx.y;
    const int t = threadIdx.x;
    const int rep = (t >> 5) & (NREP - 1);

    #pragma unroll
    for (int r = 0; r < NREP; r++) h[r][t] = 0u;
    __syncthreads();

#if __CUDA_ARCH__ >= 900
    cudaGridDependencySynchronize();   // wait for blur completion
#endif

    const float lo     = __int_as_float(g_min[b]);
    const float hi     = __int_as_float(g_max[b]);
    const float width  = (hi - lo) / 256.0f;
    const float wm     = fmaxf(width, 1e-12f);
    const float inv_wm = 1.0f / wm;

    const float4* __restrict__ p =
        reinterpret_cast<const float4*>(g_blurred + (size_t)b * HW);
    const int n4 = HW / 4;
    unsigned* __restrict__ hr = h[rep];
    #pragma unroll 2
    for (int i = blockIdx.x * 256 + t; i < n4; i += HIST_BLOCKS * 256) {
        float4 v = p[i];
        int i0 = binof(v.x, lo, inv_wm);
        int i1 = binof(v.y, lo, inv_wm);
        int i2 = binof(v.z, lo, inv_wm);
        int i3 = binof(v.w, lo, inv_wm);
        atomicAdd(&hr[i0], 1u);
        atomicAdd(&hr[i1], 1u);
        atomicAdd(&hr[i2], 1u);
        atomicAdd(&hr[i3], 1u);
    }
    __syncthreads();
    unsigned c = 0u;
    #pragma unroll
    for (int r = 0; r < NREP; r++) c += h[r][t];
    if (c) atomicAdd(&g_hist[b * NB + t], c);

    // ---- last-block election ----
    __threadfence();
    if (t == 0) {
        unsigned old = atomicAdd(&g_done[b], 1u);
        s_last = (old == HIST_BLOCKS - 1);
    }
    __syncthreads();
    if (!s_last) return;
    __threadfence();   // acquire: see all blocks' g_hist additions

    // ---- Otsu (parallel, 256 threads) ----
    const int lane = t & 31, wid = t >> 5;
    __shared__ float  s_wW[8];
    __shared__ double s_wP[8];
    __shared__ unsigned long long s_key[8];

    const float cnt    = (float)g_hist[b * NB + t];
    const float center = lo + ((float)t + 0.5f) * width;
    double cp = (double)(cnt * center);
    float  w  = cnt;

    #pragma unroll
    for (int o = 1; o < 32; o <<= 1) {
        float  wv = __shfl_up_sync(0xffffffffu, w,  o);
        double pv = __shfl_up_sync(0xffffffffu, cp, o);
        if (lane >= o) { w += wv; cp += pv; }
    }
    if (lane == 31) { s_wW[wid] = w; s_wP[wid] = cp; }
    __syncthreads();

    float offW = 0.f; double offP = 0.0;
    float totW = 0.f; double totP = 0.0;
    #pragma unroll
    for (int i = 0; i < 8; i++) {
        if (i < wid) { offW += s_wW[i]; offP += s_wP[i]; }
        totW += s_wW[i]; totP += s_wP[i];
    }
    const float  w1 = w  + offW;
    const double cs = cp + offP;

    unsigned long long key = 0ull;
    if (t < NB - 1) {
        float w2n = totW - w1;
        float m1  = (float)cs          / fmaxf(w1,  1e-12f);
        float m2  = (float)(totP - cs) / fmaxf(w2n, 1e-12f);
        float d   = m1 - m2;
        float var = w1 * w2n * d * d;
        key = ((unsigned long long)__float_as_uint(var) << 8)
              | (unsigned long long)(255 - t);
    }
    #pragma unroll
    for (int o = 16; o > 0; o >>= 1) {
        unsigned long long k2 = __shfl_xor_sync(0xffffffffu, key, o);
        key = (k2 > key) ? k2 : key;
    }
    if (lane == 0) s_key[wid] = key;
    __syncthreads();
    if (t == 0) {
        unsigned long long best = s_key[0];
        #pragma unroll
        for (int i = 1; i < 8; i++) best = (s_key[i] > best) ? s_key[i] : best;
        int bi = 255 - (int)(best & 0xffull);
        g_thresh[b] = lo + ((float)bi + 0.5f) * width;
    }
    __syncthreads();
    g_hist[b * NB + t] = 0u;             // reset for next replay
    if (t == 0) { g_min[b] = 0x7f7f7f7f; g_max[b] = 0; g_done[b] = 0u; }
}

// ---------------------------------------------------------------------------
// 3) mask + composite with PDL prefetch; 2 float4 per thread, each access
//    warp-contiguous (i and i+256) -> 8 independent LDG.128 in flight.
// ---------------------------------------------------------------------------
__global__ void final_kernel(const float* __restrict__ x, float* __restrict__ out) {
    const int b  = blockIdx.y;
    const int n4 = HW / 4;                               // 65536, % 512 == 0
    const int i0 = blockIdx.x * 512 + threadIdx.x;       // element A
    const int i1 = i0 + 256;                             // element B

    const float4* __restrict__ blr =
        reinterpret_cast<const float4*>(g_blurred + (size_t)b * HW);
    const float4* __restrict__ xin =
        reinterpret_cast<const float4*>(x + (size_t)b * 4 * HW);

    // Prefetch everything independent of the predecessor kernel.
    float4 vA = __ldcs(&blr[i0]);
    float4 vB = __ldcs(&blr[i1]);
    float4 rA0 = __ldcs(&xin[(size_t)1 * n4 + i0]);
    float4 rB0 = __ldcs(&xin[(size_t)1 * n4 + i1]);
    float4 rA1 = __ldcs(&xin[(size_t)2 * n4 + i0]);
    float4 rB1 = __ldcs(&xin[(size_t)2 * n4 + i1]);
    float4 rA2 = __ldcs(&xin[(size_t)3 * n4 + i0]);
    float4 rB2 = __ldcs(&xin[(size_t)3 * n4 + i1]);

#if __CUDA_ARCH__ >= 900
    cudaGridDependencySynchronize();   // wait for hist_otsu completion
#endif
    const float t = g_thresh[b];

    float4* __restrict__ o = reinterpret_cast<float4*>(out + (size_t)b * 3 * HW);

    #define COMPOSITE(V, R, IDX, CH) do {                                   \
        float a0 = (V).x > t ? 1.f : (V).x;                                 \
        float a1 = (V).y > t ? 1.f : (V).y;                                 \
        float a2 = (V).z > t ? 1.f : (V).z;                                 \
        float a3 = (V).w > t ? 1.f : (V).w;                                 \
        float4 res;                                                         \
        res.x = fminf(fmaxf(a0 * (R).x + (1.f - a0), 0.f), 1.f);            \
        res.y = fminf(fmaxf(a1 * (R).y + (1.f - a1), 0.f), 1.f);            \
        res.z = fminf(fmaxf(a2 * (R).z + (1.f - a2), 0.f), 1.f);            \
        res.w = fminf(fmaxf(a3 * (R).w + (1.f - a3), 0.f), 1.f);            \
        __stcs(&o[(size_t)(CH) * n4 + (IDX)], res);                         \
    } while (0)

    COMPOSITE(vA, rA0, i0, 0);
    COMPOSITE(vB, rB0, i1, 0);
    COMPOSITE(vA, rA1, i0, 1);
    COMPOSITE(vB, rB1, i1, 1);
    COMPOSITE(vA, rA2, i0, 2);
    COMPOSITE(vB, rB2, i1, 2);
    #undef COMPOSITE
}

// ---------------------------------------------------------------------------
extern "C" void kernel_launch(void* const* d_in, const int* in_sizes, int n_in,
                              void* d_out, int out_size) {
    const float* x = (const float*)d_in[0];
    float* out = (float*)d_out;
    int B = in_sizes[0] / (4 * HW);   // 32
    if (B > BMAX) B = BMAX;

    dim3 t1(VC, 4);
    dim3 g1(W / TW, H / TH, B);
    blur_kernel<<<g1, t1>>>(x);

    cudaLaunchAttribute attr[1];
    attr[0].id = cudaLaunchAttributeProgrammaticStreamSerialization;
    attr[0].val.programmaticStreamSerializationAllowed = 1;

    // hist_otsu with PDL
    dim3 g2(HIST_BLOCKS, B);
    cudaLaunchConfig_t cfg2 = {};
    cfg2.gridDim  = g2;
    cfg2.blockDim = dim3(256, 1, 1);
    cfg2.stream = 0;
    cfg2.attrs = attr;
    cfg2.numAttrs = 1;
    if (cudaLaunchKernelEx(&cfg2, hist_otsu_kernel) != cudaSuccess)
        hist_otsu_kernel<<<g2, 256>>>();

    // final with PDL (2 float4 per thread -> half the blocks)
    dim3 g4(HW / 4 / 512, B);   // 128 x 32
    cudaLaunchConfig_t cfg3 = {};
    cfg3.gridDim  = g4;
    cfg3.blockDim = dim3(256, 1, 1);
    cfg3.stream = 0;
    cfg3.attrs = attr;
    cfg3.numAttrs = 1;
    if (cudaLaunchKernelEx(&cfg3, final_kernel, x, out) != cudaSuccess)
        final_kernel<<<g4, 256>>>(x, out);
}